// round 7
// baseline (speedup 1.0000x reference)
#include <cuda_runtime.h>
#include <cuda_fp16.h>
#include <cstdint>

#define NN 50000
#define NE 800000
#define FIN 8          // concat(x[6], pos[2])
#define HID 64
#define NOUT 10
#define P16 16         // padded layer-3 feature width
#define NK 4           // K+1 weight slices
#define NSCANB 196     // ceil(NN/256)

typedef unsigned long long ull;

// ---------------- scratch (no allocation allowed) ----------------
struct Scratch {
    alignas(128) float deg[NN];
    alignas(128) float dinv[NN];
    alignas(128) int   cnt[NN];
    alignas(128) int   rowptr[NN + 1];
    alignas(128) int   cursor[NN];
    alignas(128) int   bsum[256];
    alignas(128) int2  edg[NE];           // (src, bitcast(norm))
    alignas(128) float h0 [NN * FIN];
    alignas(128) float t8a[NN * FIN];
    alignas(128) float t8b[NN * FIN];
    alignas(128) float t8c[NN * FIN];
    alignas(128) __half2 h16A[NN * HID / 2];
    alignas(128) __half2 h16B[NN * HID / 2];
    alignas(128) __half2 h16C[NN * HID / 2];
    alignas(128) __half2 h16D[NN * HID / 2];
    alignas(128) float g0[NN * P16];
    alignas(128) float g1[NN * P16];
    alignas(128) float g2[NN * P16];
    alignas(128) float g3[NN * P16];
    alignas(128) float p16a[NN * P16];
    alignas(128) float p16b[NN * P16];
};
__device__ Scratch g_s;
__device__ int g_is64;

// ---------------- f32x2 packed helpers ----------------
__device__ __forceinline__ ull dup2(float v) {
    ull r; unsigned int b = __float_as_uint(v);
    asm("mov.b64 %0, {%1, %1};" : "=l"(r) : "r"(b));
    return r;
}
__device__ __forceinline__ void fma2(ull& d, ull a, ull b) {
    asm("fma.rn.f32x2 %0, %1, %2, %0;" : "+l"(d) : "l"(a), "l"(b));
}
__device__ __forceinline__ float2 unpack2(ull v) {
    float2 u;
    asm("mov.b64 {%0, %1}, %2;" : "=f"(u.x), "=f"(u.y) : "l"(v));
    return u;
}

// ---------------- edge_index dtype detection ----------------
__global__ void k_detect(const int* __restrict__ ei32) {
    int t = threadIdx.x;
    const int step = NE / 1024;
    long long idx = 2LL * t * step + 1;
    int nz = (ei32[idx] != 0) ? 1 : 0;
    int any = __syncthreads_or(nz);
    if (t == 0) g_is64 = any ? 0 : 1;
}

__device__ __forceinline__ int load_src(const int* ei32, int e, int is64) {
    int v = is64 ? ei32[2 * e] : ei32[e];
    return min(max(v, 0), NN - 1);
}
__device__ __forceinline__ int load_dst(const int* ei32, int e, int is64) {
    long long base = is64 ? 2LL * ((long long)NE + e) : (long long)NE + e;
    int v = ei32[base];
    return min(max(v, 0), NN - 1);
}

// ---------------- graph preprocessing ----------------
__global__ void k_zero_concat(const float* __restrict__ x, const float* __restrict__ pos,
                              float* __restrict__ h0,
                              float* __restrict__ deg, int* __restrict__ cnt) {
    int i = blockIdx.x * blockDim.x + threadIdx.x;
    if (i >= NN) return;
    deg[i] = 0.0f; cnt[i] = 0;
    float* o = h0 + i * FIN;
    const float* xi = x + i * 6;
    o[0] = xi[0]; o[1] = xi[1]; o[2] = xi[2];
    o[3] = xi[3]; o[4] = xi[4]; o[5] = xi[5];
    o[6] = pos[i * 2 + 0];
    o[7] = pos[i * 2 + 1];
}

__global__ void k_deg_cnt(const int* __restrict__ ei32,
                          const float* __restrict__ ea,
                          float* __restrict__ deg, int* __restrict__ cnt) {
    int e = blockIdx.x * blockDim.x + threadIdx.x;
    if (e >= NE) return;
    int is64 = g_is64;
    int d = load_dst(ei32, e, is64);
    atomicAdd(&deg[d], ea[e]);
    atomicAdd(&cnt[d], 1);
}

__global__ void k_scan1(const int* __restrict__ cnt,
                        int* __restrict__ partial, int* __restrict__ bsum) {
    int i = blockIdx.x * 256 + threadIdx.x;
    int lane = threadIdx.x & 31, wid = threadIdx.x >> 5;
    int v = (i < NN) ? cnt[i] : 0;
    int x = v;
    #pragma unroll
    for (int o = 1; o < 32; o <<= 1) {
        int n = __shfl_up_sync(0xFFFFFFFFu, x, o);
        if (lane >= o) x += n;
    }
    __shared__ int ws[8];
    if (lane == 31) ws[wid] = x;
    __syncthreads();
    if (threadIdx.x < 8) {
        int w = ws[threadIdx.x];
        #pragma unroll
        for (int o = 1; o < 8; o <<= 1) {
            int n = __shfl_up_sync(0xFFu, w, o);
            if ((threadIdx.x & 7) >= o) w += n;
        }
        ws[threadIdx.x] = w;
    }
    __syncthreads();
    int excl = x - v + (wid > 0 ? ws[wid - 1] : 0);
    if (i < NN) partial[i] = excl;
    if (threadIdx.x == 255) bsum[blockIdx.x] = excl + v;
}

__global__ void k_scan2(int* __restrict__ bsum) {
    int t = threadIdx.x;
    int lane = t & 31, wid = t >> 5;
    int v = (t < NSCANB) ? bsum[t] : 0;
    int x = v;
    #pragma unroll
    for (int o = 1; o < 32; o <<= 1) {
        int n = __shfl_up_sync(0xFFFFFFFFu, x, o);
        if (lane >= o) x += n;
    }
    __shared__ int ws[8];
    if (lane == 31) ws[wid] = x;
    __syncthreads();
    if (t < 8) {
        int w = ws[t];
        #pragma unroll
        for (int o = 1; o < 8; o <<= 1) {
            int n = __shfl_up_sync(0xFFu, w, o);
            if ((t & 7) >= o) w += n;
        }
        ws[t] = w;
    }
    __syncthreads();
    int excl = x - v + (wid > 0 ? ws[wid - 1] : 0);
    if (t < NSCANB) bsum[t] = excl;
}

__global__ void k_scan3(int* __restrict__ rowptr, int* __restrict__ cursor,
                        const int* __restrict__ bsum,
                        const float* __restrict__ deg, float* __restrict__ dinv) {
    int i = blockIdx.x * 256 + threadIdx.x;
    if (i >= NN) return;
    int r = rowptr[i] + bsum[blockIdx.x];
    rowptr[i] = r;
    cursor[i] = r;
    float d = deg[i];
    dinv[i] = (d > 0.0f) ? rsqrtf(d) : 0.0f;
    if (i == 0) rowptr[NN] = NE;
}

__global__ void k_fill(const int* __restrict__ ei32,
                       const float* __restrict__ ea,
                       const float* __restrict__ dinv,
                       int* __restrict__ cursor, int2* __restrict__ edg) {
    int e = blockIdx.x * blockDim.x + threadIdx.x;
    if (e >= NE) return;
    int is64 = g_is64;
    int srcv = load_src(ei32, e, is64);
    int dstv = load_dst(ei32, e, is64);
    float nv = dinv[srcv] * ea[e] * dinv[dstv];
    int p = atomicAdd(&cursor[dstv], 1);
    edg[p] = make_int2(srcv, __float_as_int(nv));
}

// ---------------- propagate (CSR gather, pull) ----------------
template<int W>
__global__ void k_propW(const float* __restrict__ h, const float* __restrict__ add,
                        float* __restrict__ o,
                        const int* __restrict__ rowptr, const int2* __restrict__ edg) {
    const int GPW = 32 / W;
    int warp = blockIdx.x * (blockDim.x >> 5) + (threadIdx.x >> 5);
    int lane = threadIdx.x & 31;
    int node = warp * GPW + lane / W;
    int f = lane % W;
    if (node >= NN) return;
    int b = rowptr[node], e = rowptr[node + 1];
    float acc = add ? add[node * W + f] : 0.0f;
    for (int i = b; i < e; i++) {
        int2 ev = edg[i];
        acc += __int_as_float(ev.y) * h[ev.x * W + f];
    }
    o[node * W + f] = acc;
}

// fp16 warp-per-node: lane f holds features {2f, 2f+1}; one 128B line per edge
__global__ void k_prop64h(const __half2* __restrict__ h, __half2* __restrict__ o,
                          const int* __restrict__ rowptr, const int2* __restrict__ edg) {
    int node = blockIdx.x * (blockDim.x >> 5) + (threadIdx.x >> 5);
    int lane = threadIdx.x & 31;
    if (node >= NN) return;
    int b = rowptr[node], e = rowptr[node + 1];
    float a0 = 0.0f, a1 = 0.0f;
    #pragma unroll 2
    for (int i = b; i < e; i++) {
        int2 ev = edg[i];
        float v = __int_as_float(ev.y);
        float2 f2 = __half22float2(h[ev.x * 32 + lane]);
        a0 += v * f2.x;
        a1 += v * f2.y;
    }
    o[node * 32 + lane] = __floats2half2_rn(a0, a1);
}

// final Horner propagate + log_softmax via width-16 shuffle reduction
__global__ void k_prop16_lsm(const float* __restrict__ h, const float* __restrict__ add,
                             float* __restrict__ outp,
                             const int* __restrict__ rowptr, const int2* __restrict__ edg) {
    int warp = blockIdx.x * (blockDim.x >> 5) + (threadIdx.x >> 5);
    int lane = threadIdx.x & 31;
    int node = warp * 2 + (lane >> 4);
    int f = lane & 15;
    if (node >= NN) return;
    int b = rowptr[node], e = rowptr[node + 1];
    float acc = add[node * P16 + f];
    for (int i = b; i < e; i++) {
        int2 ev = edg[i];
        acc += __int_as_float(ev.y) * h[ev.x * P16 + f];
    }
    float mv = (f < NOUT) ? acc : -1e30f;
    #pragma unroll
    for (int o = 8; o >= 1; o >>= 1)
        mv = fmaxf(mv, __shfl_xor_sync(0xFFFFFFFFu, mv, o, 16));
    float ex = (f < NOUT) ? expf(acc - mv) : 0.0f;
    float s = ex;
    #pragma unroll
    for (int o = 8; o >= 1; o >>= 1)
        s += __shfl_xor_sync(0xFFFFFFFFu, s, o, 16);
    float l = mv + logf(s);
    if (f < NOUT) outp[node * NOUT + f] = acc - l;
}

// ---------------- layer-1 GEMM (f32x2), fp16 output ----------------
__global__ void k_gemm_l1(const float* __restrict__ h0, const float* __restrict__ h1,
                          const float* __restrict__ h2, const float* __restrict__ h3,
                          const float* __restrict__ W, const float* __restrict__ bias,
                          __half2* __restrict__ outp) {
    __shared__ alignas(16) float sW[NK * FIN * HID];
    __shared__ alignas(16) float sb[HID];
    for (int i = threadIdx.x; i < NK * FIN * HID; i += blockDim.x) sW[i] = W[i];
    if (threadIdx.x < HID) sb[threadIdx.x] = bias[threadIdx.x];
    __syncthreads();

    int row = blockIdx.x * blockDim.x + threadIdx.x;
    if (row >= NN) return;
    const float* hs[NK] = {h0 + row * FIN, h1 + row * FIN, h2 + row * FIN, h3 + row * FIN};

    ull acc2[HID / 2];
    const ull* sb64 = (const ull*)sb;
    #pragma unroll
    for (int c = 0; c < HID / 2; c++) acc2[c] = sb64[c];

    #pragma unroll
    for (int kk = 0; kk < NK; kk++) {
        const float4* hp = (const float4*)hs[kk];
        float4 h04 = hp[0], h14 = hp[1];
        float hv[FIN] = {h04.x, h04.y, h04.z, h04.w, h14.x, h14.y, h14.z, h14.w};
        #pragma unroll
        for (int k = 0; k < FIN; k++) {
            ull hd = dup2(hv[k]);
            const ulonglong2* w2 = (const ulonglong2*)(sW + (kk * FIN + k) * HID);
            #pragma unroll
            for (int c = 0; c < HID / 4; c++) {
                ulonglong2 wp = w2[c];
                fma2(acc2[2 * c], wp.x, hd);
                fma2(acc2[2 * c + 1], wp.y, hd);
            }
        }
    }
    __half2* op = outp + row * 32;        // pair c -> features (2c, 2c+1)
    #pragma unroll
    for (int c = 0; c < HID / 2; c++) {
        float2 u = unpack2(acc2[c]);
        op[c] = __floats2half2_rn(fmaxf(u.x, 0.f), fmaxf(u.y, 0.f));
    }
}

// ---------------- layer-2 GEMM + layer-3 transform, fused ----------------
// g_k = relu(sum_kk A^kk-hops @ W2 + b2) @ W3[k]  (bias b3 folded into g0)
__global__ void k_gemm_l2tx3(const __half2* __restrict__ h0, const __half2* __restrict__ h1,
                             const __half2* __restrict__ h2, const __half2* __restrict__ h3,
                             const float* __restrict__ W2, const float* __restrict__ b2,
                             const float* __restrict__ W3, const float* __restrict__ b3,
                             float* __restrict__ g0, float* __restrict__ g1,
                             float* __restrict__ g2, float* __restrict__ g3) {
    extern __shared__ float sW[];                  // 64KB: W2
    __shared__ alignas(16) float sb[HID];
    __shared__ float sW3[NK * HID * NOUT];         // 10KB
    __shared__ float sb3[NOUT];
    for (int i = threadIdx.x; i < NK * HID * HID; i += blockDim.x) sW[i] = W2[i];
    for (int i = threadIdx.x; i < NK * HID * NOUT; i += blockDim.x) sW3[i] = W3[i];
    if (threadIdx.x < HID) sb[threadIdx.x] = b2[threadIdx.x];
    if (threadIdx.x < NOUT) sb3[threadIdx.x] = b3[threadIdx.x];
    __syncthreads();

    int row = blockIdx.x * blockDim.x + threadIdx.x;
    if (row >= NN) return;
    const __half2* hs[NK] = {h0 + row * 32, h1 + row * 32, h2 + row * 32, h3 + row * 32};

    ull acc2[HID / 2];                             // pair m -> out features (2m, 2m+1)
    const ull* sb64 = (const ull*)sb;
    #pragma unroll
    for (int c = 0; c < HID / 2; c++) acc2[c] = sb64[c];

    for (int kk = 0; kk < NK; kk++) {
        const __half2* hp = hs[kk];
        #pragma unroll 8
        for (int j = 0; j < 32; j++) {             // input features 2j, 2j+1
            float2 hv = __half22float2(hp[j]);
            ull hd0 = dup2(hv.x), hd1 = dup2(hv.y);
            const ulonglong2* w0 = (const ulonglong2*)(sW + (kk * HID + 2 * j) * HID);
            const ulonglong2* w1 = (const ulonglong2*)(sW + (kk * HID + 2 * j + 1) * HID);
            #pragma unroll
            for (int c = 0; c < HID / 4; c++) {
                ulonglong2 p0 = w0[c];
                fma2(acc2[2 * c],     p0.x, hd0);
                fma2(acc2[2 * c + 1], p0.y, hd0);
                ulonglong2 p1 = w1[c];
                fma2(acc2[2 * c],     p1.x, hd1);
                fma2(acc2[2 * c + 1], p1.y, hd1);
            }
        }
    }

    // relu + tx3 epilogue
    float acc3[NK * NOUT];
    #pragma unroll
    for (int kk = 0; kk < NK; kk++)
        #pragma unroll
        for (int c = 0; c < NOUT; c++)
            acc3[kk * NOUT + c] = (kk == 0) ? sb3[c] : 0.0f;

    #pragma unroll 4
    for (int j = 0; j < HID / 2; j++) {            // hidden features 2j, 2j+1
        float2 u = unpack2(acc2[j]);
        float f0 = fmaxf(u.x, 0.f), f1 = fmaxf(u.y, 0.f);
        #pragma unroll
        for (int kk = 0; kk < NK; kk++) {
            const float* w = sW3 + (kk * HID + 2 * j) * NOUT;
            #pragma unroll
            for (int c = 0; c < NOUT; c++)
                acc3[kk * NOUT + c] += f0 * w[c] + f1 * w[NOUT + c];
        }
    }
    float* gs[NK] = {g0 + row * P16, g1 + row * P16, g2 + row * P16, g3 + row * P16};
    #pragma unroll
    for (int kk = 0; kk < NK; kk++) {
        #pragma unroll
        for (int c = 0; c < NOUT; c++) gs[kk][c] = acc3[kk * NOUT + c];
        #pragma unroll
        for (int c = NOUT; c < P16; c++) gs[kk][c] = 0.0f;
    }
}

// ---------------- launch ----------------
extern "C" void kernel_launch(void* const* d_in, const int* in_sizes, int n_in,
                              void* d_out, int out_size) {
    const float *x = 0, *pos = 0, *ea = 0, *W1 = 0, *b1 = 0, *W2 = 0, *b2 = 0,
                *W3 = 0, *b3 = 0;
    const int* ei32 = 0;
    for (int i = 0; i < n_in; i++) {
        switch (in_sizes[i]) {
            case 1600000: ei32 = (const int*)d_in[i]; break;
            case  800000: ea  = (const float*)d_in[i]; break;
            case  300000: x   = (const float*)d_in[i]; break;
            case  100000: pos = (const float*)d_in[i]; break;
            case    2048: W1  = (const float*)d_in[i]; break;
            case   16384: W2  = (const float*)d_in[i]; break;
            case    2560: W3  = (const float*)d_in[i]; break;
            case      10: b3  = (const float*)d_in[i]; break;
            case      64:
                if (!b1) b1 = (const float*)d_in[i];
                else     b2 = (const float*)d_in[i];
                break;
            default: break;
        }
    }
    float* out = (float*)d_out;

    Scratch* S;
    cudaGetSymbolAddress((void**)&S, g_s);
    cudaFuncSetAttribute(k_gemm_l2tx3, cudaFuncAttributeMaxDynamicSharedMemorySize,
                         NK * HID * HID * (int)sizeof(float));

    const int BE = (NE + 255) / 256;
    const int BN = (NN + 255) / 256;
    const int BG = (NN + 127) / 128;
    const int BG2 = (NN + 255) / 256;
    const int BW = (NN + 7) / 8;
    const int B8  = (NN + 31) / 32;
    const int B16 = (NN + 15) / 16;

    k_detect<<<1, 1024>>>(ei32);
    k_zero_concat<<<BN, 256>>>(x, pos, S->h0, S->deg, S->cnt);
    k_deg_cnt<<<BE, 256>>>(ei32, ea, S->deg, S->cnt);
    k_scan1<<<NSCANB, 256>>>(S->cnt, S->rowptr, S->bsum);
    k_scan2<<<1, 256>>>(S->bsum);
    k_scan3<<<NSCANB, 256>>>(S->rowptr, S->cursor, S->bsum, S->deg, S->dinv);
    k_fill<<<BE, 256>>>(ei32, ea, S->dinv, S->cursor, S->edg);

    // layer 1 (F=8 -> 64), fp16 output
    k_propW<8><<<B8, 256>>>(S->h0,  nullptr, S->t8a, S->rowptr, S->edg);
    k_propW<8><<<B8, 256>>>(S->t8a, nullptr, S->t8b, S->rowptr, S->edg);
    k_propW<8><<<B8, 256>>>(S->t8b, nullptr, S->t8c, S->rowptr, S->edg);
    k_gemm_l1<<<BG, 128>>>(S->h0, S->t8a, S->t8b, S->t8c, W1, b1, S->h16A);

    // layer 2 hops in fp16 (one 128B line per edge)
    k_prop64h<<<BW, 256>>>(S->h16A, S->h16B, S->rowptr, S->edg);
    k_prop64h<<<BW, 256>>>(S->h16B, S->h16C, S->rowptr, S->edg);
    k_prop64h<<<BW, 256>>>(S->h16C, S->h16D, S->rowptr, S->edg);

    // layer-2 GEMM + layer-3 transform fused -> g0..g3
    k_gemm_l2tx3<<<BG2, 256, NK * HID * HID * (int)sizeof(float)>>>(
        S->h16A, S->h16B, S->h16C, S->h16D, W2, b2, W3, b3,
        S->g0, S->g1, S->g2, S->g3);

    // layer 3 Horner propagate at width 16 + fused log-softmax
    k_propW<16><<<B16, 256>>>(S->g3,  S->g2, S->p16a, S->rowptr, S->edg);
    k_propW<16><<<B16, 256>>>(S->p16a, S->g1, S->p16b, S->rowptr, S->edg);
    k_prop16_lsm<<<B16, 256>>>(S->p16b, S->g0, out, S->rowptr, S->edg);
}

// round 8
// speedup vs baseline: 1.0192x; 1.0192x over previous
#include <cuda_runtime.h>
#include <cuda_fp16.h>
#include <cstdint>

#define NN 50000
#define NE 800000
#define FIN 8          // concat(x[6], pos[2])
#define HID 64
#define NOUT 10
#define P16 16         // padded layer-3 feature width
#define NK 4           // K+1 weight slices
#define NSCANB 196     // ceil(NN/256)

typedef unsigned long long ull;

// ---------------- scratch (no allocation allowed) ----------------
struct Scratch {
    alignas(128) float deg[NN];
    alignas(128) float dinv[NN];
    alignas(128) int   cnt[NN];
    alignas(128) int   rowptr[NN + 1];
    alignas(128) int   cursor[NN];
    alignas(128) int   bsum[256];
    alignas(128) int2  edg[NE];           // (src, bitcast(norm))
    alignas(128) float h0 [NN * FIN];
    alignas(128) float t8a[NN * FIN];
    alignas(128) float t8b[NN * FIN];
    alignas(128) float t8c[NN * FIN];
    alignas(128) __half2 h16A[NN * HID / 2];
    alignas(128) __half2 h16B[NN * HID / 2];
    alignas(128) __half2 h16C[NN * HID / 2];
    alignas(128) __half2 h16D[NN * HID / 2];
    alignas(128) float hA[NN * HID];      // fp32 layer-2 output (tx3 input)
    alignas(128) float g0[NN * P16];
    alignas(128) float g1[NN * P16];
    alignas(128) float g2[NN * P16];
    alignas(128) float g3[NN * P16];
    alignas(128) float p16a[NN * P16];
    alignas(128) float p16b[NN * P16];
};
__device__ Scratch g_s;
__device__ int g_is64;

// ---------------- f32x2 packed helpers ----------------
__device__ __forceinline__ ull dup2(float v) {
    ull r; unsigned int b = __float_as_uint(v);
    asm("mov.b64 %0, {%1, %1};" : "=l"(r) : "r"(b));
    return r;
}
__device__ __forceinline__ void fma2(ull& d, ull a, ull b) {
    asm("fma.rn.f32x2 %0, %1, %2, %0;" : "+l"(d) : "l"(a), "l"(b));
}
__device__ __forceinline__ float2 unpack2(ull v) {
    float2 u;
    asm("mov.b64 {%0, %1}, %2;" : "=f"(u.x), "=f"(u.y) : "l"(v));
    return u;
}

// ---------------- edge_index dtype detection ----------------
__global__ void k_detect(const int* __restrict__ ei32) {
    int t = threadIdx.x;
    const int step = NE / 1024;
    long long idx = 2LL * t * step + 1;
    int nz = (ei32[idx] != 0) ? 1 : 0;
    int any = __syncthreads_or(nz);
    if (t == 0) g_is64 = any ? 0 : 1;
}

__device__ __forceinline__ int load_src(const int* ei32, int e, int is64) {
    int v = is64 ? ei32[2 * e] : ei32[e];
    return min(max(v, 0), NN - 1);
}
__device__ __forceinline__ int load_dst(const int* ei32, int e, int is64) {
    long long base = is64 ? 2LL * ((long long)NE + e) : (long long)NE + e;
    int v = ei32[base];
    return min(max(v, 0), NN - 1);
}

// ---------------- graph preprocessing ----------------
__global__ void k_zero_concat(const float* __restrict__ x, const float* __restrict__ pos,
                              float* __restrict__ h0,
                              float* __restrict__ deg, int* __restrict__ cnt) {
    int i = blockIdx.x * blockDim.x + threadIdx.x;
    if (i >= NN) return;
    deg[i] = 0.0f; cnt[i] = 0;
    float* o = h0 + i * FIN;
    const float* xi = x + i * 6;
    o[0] = xi[0]; o[1] = xi[1]; o[2] = xi[2];
    o[3] = xi[3]; o[4] = xi[4]; o[5] = xi[5];
    o[6] = pos[i * 2 + 0];
    o[7] = pos[i * 2 + 1];
}

__global__ void k_deg_cnt(const int* __restrict__ ei32,
                          const float* __restrict__ ea,
                          float* __restrict__ deg, int* __restrict__ cnt) {
    int e = blockIdx.x * blockDim.x + threadIdx.x;
    if (e >= NE) return;
    int is64 = g_is64;
    int d = load_dst(ei32, e, is64);
    atomicAdd(&deg[d], ea[e]);
    atomicAdd(&cnt[d], 1);
}

__global__ void k_scan1(const int* __restrict__ cnt,
                        int* __restrict__ partial, int* __restrict__ bsum) {
    int i = blockIdx.x * 256 + threadIdx.x;
    int lane = threadIdx.x & 31, wid = threadIdx.x >> 5;
    int v = (i < NN) ? cnt[i] : 0;
    int x = v;
    #pragma unroll
    for (int o = 1; o < 32; o <<= 1) {
        int n = __shfl_up_sync(0xFFFFFFFFu, x, o);
        if (lane >= o) x += n;
    }
    __shared__ int ws[8];
    if (lane == 31) ws[wid] = x;
    __syncthreads();
    if (threadIdx.x < 8) {
        int w = ws[threadIdx.x];
        #pragma unroll
        for (int o = 1; o < 8; o <<= 1) {
            int n = __shfl_up_sync(0xFFu, w, o);
            if ((threadIdx.x & 7) >= o) w += n;
        }
        ws[threadIdx.x] = w;
    }
    __syncthreads();
    int excl = x - v + (wid > 0 ? ws[wid - 1] : 0);
    if (i < NN) partial[i] = excl;
    if (threadIdx.x == 255) bsum[blockIdx.x] = excl + v;
}

__global__ void k_scan2(int* __restrict__ bsum) {
    int t = threadIdx.x;
    int lane = t & 31, wid = t >> 5;
    int v = (t < NSCANB) ? bsum[t] : 0;
    int x = v;
    #pragma unroll
    for (int o = 1; o < 32; o <<= 1) {
        int n = __shfl_up_sync(0xFFFFFFFFu, x, o);
        if (lane >= o) x += n;
    }
    __shared__ int ws[8];
    if (lane == 31) ws[wid] = x;
    __syncthreads();
    if (t < 8) {
        int w = ws[t];
        #pragma unroll
        for (int o = 1; o < 8; o <<= 1) {
            int n = __shfl_up_sync(0xFFu, w, o);
            if ((t & 7) >= o) w += n;
        }
        ws[t] = w;
    }
    __syncthreads();
    int excl = x - v + (wid > 0 ? ws[wid - 1] : 0);
    if (t < NSCANB) bsum[t] = excl;
}

__global__ void k_scan3(int* __restrict__ rowptr, int* __restrict__ cursor,
                        const int* __restrict__ bsum,
                        const float* __restrict__ deg, float* __restrict__ dinv) {
    int i = blockIdx.x * 256 + threadIdx.x;
    if (i >= NN) return;
    int r = rowptr[i] + bsum[blockIdx.x];
    rowptr[i] = r;
    cursor[i] = r;
    float d = deg[i];
    dinv[i] = (d > 0.0f) ? rsqrtf(d) : 0.0f;
    if (i == 0) rowptr[NN] = NE;
}

__global__ void k_fill(const int* __restrict__ ei32,
                       const float* __restrict__ ea,
                       const float* __restrict__ dinv,
                       int* __restrict__ cursor, int2* __restrict__ edg) {
    int e = blockIdx.x * blockDim.x + threadIdx.x;
    if (e >= NE) return;
    int is64 = g_is64;
    int srcv = load_src(ei32, e, is64);
    int dstv = load_dst(ei32, e, is64);
    float nv = dinv[srcv] * ea[e] * dinv[dstv];
    int p = atomicAdd(&cursor[dstv], 1);
    edg[p] = make_int2(srcv, __float_as_int(nv));
}

// ---------------- propagate (CSR gather, pull) ----------------
template<int W>
__global__ void k_propW(const float* __restrict__ h, const float* __restrict__ add,
                        float* __restrict__ o,
                        const int* __restrict__ rowptr, const int2* __restrict__ edg) {
    const int GPW = 32 / W;
    int warp = blockIdx.x * (blockDim.x >> 5) + (threadIdx.x >> 5);
    int lane = threadIdx.x & 31;
    int node = warp * GPW + lane / W;
    int f = lane % W;
    if (node >= NN) return;
    int b = rowptr[node], e = rowptr[node + 1];
    float acc = add ? add[node * W + f] : 0.0f;
    for (int i = b; i < e; i++) {
        int2 ev = edg[i];
        acc += __int_as_float(ev.y) * h[ev.x * W + f];
    }
    o[node * W + f] = acc;
}

// fp16 warp-per-node: lane f holds features {2f, 2f+1}; one 128B line per edge
__global__ void k_prop64h(const __half2* __restrict__ h, __half2* __restrict__ o,
                          const int* __restrict__ rowptr, const int2* __restrict__ edg) {
    int node = blockIdx.x * (blockDim.x >> 5) + (threadIdx.x >> 5);
    int lane = threadIdx.x & 31;
    if (node >= NN) return;
    int b = rowptr[node], e = rowptr[node + 1];
    float a0 = 0.0f, a1 = 0.0f;
    #pragma unroll 2
    for (int i = b; i < e; i++) {
        int2 ev = edg[i];
        float v = __int_as_float(ev.y);
        float2 f2 = __half22float2(h[ev.x * 32 + lane]);
        a0 += v * f2.x;
        a1 += v * f2.y;
    }
    o[node * 32 + lane] = __floats2half2_rn(a0, a1);
}

// final Horner propagate + log_softmax via width-16 shuffle reduction
__global__ void k_prop16_lsm(const float* __restrict__ h, const float* __restrict__ add,
                             float* __restrict__ outp,
                             const int* __restrict__ rowptr, const int2* __restrict__ edg) {
    int warp = blockIdx.x * (blockDim.x >> 5) + (threadIdx.x >> 5);
    int lane = threadIdx.x & 31;
    int node = warp * 2 + (lane >> 4);
    int f = lane & 15;
    if (node >= NN) return;
    int b = rowptr[node], e = rowptr[node + 1];
    float acc = add[node * P16 + f];
    for (int i = b; i < e; i++) {
        int2 ev = edg[i];
        acc += __int_as_float(ev.y) * h[ev.x * P16 + f];
    }
    float mv = (f < NOUT) ? acc : -1e30f;
    #pragma unroll
    for (int o = 8; o >= 1; o >>= 1)
        mv = fmaxf(mv, __shfl_xor_sync(0xFFFFFFFFu, mv, o, 16));
    float ex = (f < NOUT) ? expf(acc - mv) : 0.0f;
    float s = ex;
    #pragma unroll
    for (int o = 8; o >= 1; o >>= 1)
        s += __shfl_xor_sync(0xFFFFFFFFu, s, o, 16);
    float l = mv + logf(s);
    if (f < NOUT) outp[node * NOUT + f] = acc - l;
}

// ---------------- layer-1 GEMM (f32x2), fp16 output ----------------
__global__ void k_gemm_l1(const float* __restrict__ h0, const float* __restrict__ h1,
                          const float* __restrict__ h2, const float* __restrict__ h3,
                          const float* __restrict__ W, const float* __restrict__ bias,
                          __half2* __restrict__ outp) {
    __shared__ alignas(16) float sW[NK * FIN * HID];
    __shared__ alignas(16) float sb[HID];
    for (int i = threadIdx.x; i < NK * FIN * HID; i += blockDim.x) sW[i] = W[i];
    if (threadIdx.x < HID) sb[threadIdx.x] = bias[threadIdx.x];
    __syncthreads();

    int row = blockIdx.x * blockDim.x + threadIdx.x;
    if (row >= NN) return;
    const float* hs[NK] = {h0 + row * FIN, h1 + row * FIN, h2 + row * FIN, h3 + row * FIN};

    ull acc2[HID / 2];
    const ull* sb64 = (const ull*)sb;
    #pragma unroll
    for (int c = 0; c < HID / 2; c++) acc2[c] = sb64[c];

    #pragma unroll
    for (int kk = 0; kk < NK; kk++) {
        const float4* hp = (const float4*)hs[kk];
        float4 h04 = hp[0], h14 = hp[1];
        float hv[FIN] = {h04.x, h04.y, h04.z, h04.w, h14.x, h14.y, h14.z, h14.w};
        #pragma unroll
        for (int k = 0; k < FIN; k++) {
            ull hd = dup2(hv[k]);
            const ulonglong2* w2 = (const ulonglong2*)(sW + (kk * FIN + k) * HID);
            #pragma unroll
            for (int c = 0; c < HID / 4; c++) {
                ulonglong2 wp = w2[c];
                fma2(acc2[2 * c], wp.x, hd);
                fma2(acc2[2 * c + 1], wp.y, hd);
            }
        }
    }
    __half2* op = outp + row * 32;        // pair c -> features (2c, 2c+1)
    #pragma unroll
    for (int c = 0; c < HID / 2; c++) {
        float2 u = unpack2(acc2[c]);
        op[c] = __floats2half2_rn(fmaxf(u.x, 0.f), fmaxf(u.y, 0.f));
    }
}

// ---------------- layer-2 GEMM (f32x2, fp16 inputs, fp32 output) ----------------
__global__ void k_gemm_l2(const __half2* __restrict__ h0, const __half2* __restrict__ h1,
                          const __half2* __restrict__ h2, const __half2* __restrict__ h3,
                          const float* __restrict__ W, const float* __restrict__ bias,
                          float* __restrict__ outp) {
    extern __shared__ float sW[];          // 64KB
    __shared__ alignas(16) float sb[HID];
    for (int i = threadIdx.x; i < NK * HID * HID; i += blockDim.x) sW[i] = W[i];
    if (threadIdx.x < HID) sb[threadIdx.x] = bias[threadIdx.x];
    __syncthreads();

    int row = blockIdx.x * blockDim.x + threadIdx.x;
    if (row >= NN) return;
    const __half2* hs[NK] = {h0 + row * 32, h1 + row * 32, h2 + row * 32, h3 + row * 32};

    ull acc2[HID / 2];
    const ull* sb64 = (const ull*)sb;
    #pragma unroll
    for (int c = 0; c < HID / 2; c++) acc2[c] = sb64[c];

    for (int kk = 0; kk < NK; kk++) {
        const __half2* hp = hs[kk];
        #pragma unroll 4
        for (int j = 0; j < 32; j++) {     // input features 2j, 2j+1
            float2 hv = __half22float2(hp[j]);
            ull hd0 = dup2(hv.x), hd1 = dup2(hv.y);
            const ulonglong2* w0 = (const ulonglong2*)(sW + (kk * HID + 2 * j) * HID);
            const ulonglong2* w1 = (const ulonglong2*)(sW + (kk * HID + 2 * j + 1) * HID);
            #pragma unroll
            for (int c = 0; c < HID / 4; c++) {
                ulonglong2 p0 = w0[c];
                fma2(acc2[2 * c],     p0.x, hd0);
                fma2(acc2[2 * c + 1], p0.y, hd0);
                ulonglong2 p1 = w1[c];
                fma2(acc2[2 * c],     p1.x, hd1);
                fma2(acc2[2 * c + 1], p1.y, hd1);
            }
        }
    }
    float4* op = (float4*)(outp + row * HID);
    #pragma unroll
    for (int c = 0; c < HID / 4; c++) {
        float2 u0 = unpack2(acc2[2 * c]), u1 = unpack2(acc2[2 * c + 1]);
        op[c] = make_float4(fmaxf(u0.x, 0.f), fmaxf(u0.y, 0.f),
                            fmaxf(u1.x, 0.f), fmaxf(u1.y, 0.f));
    }
}

// layer-3 transforms: g_k = h @ W3[k] (bias folded into g0); pad to 16
__global__ void k_tx3(const float* __restrict__ h, const float* __restrict__ W,
                      const float* __restrict__ bias,
                      float* __restrict__ g0, float* __restrict__ g1,
                      float* __restrict__ g2, float* __restrict__ g3) {
    __shared__ float sW[NK * HID * NOUT];
    __shared__ float sb[NOUT];
    for (int i = threadIdx.x; i < NK * HID * NOUT; i += blockDim.x) sW[i] = W[i];
    if (threadIdx.x < NOUT) sb[threadIdx.x] = bias[threadIdx.x];
    __syncthreads();

    int row = blockIdx.x * blockDim.x + threadIdx.x;
    if (row >= NN) return;
    const float4* hp = (const float4*)(h + row * HID);

    float acc[NK * NOUT];
    #pragma unroll
    for (int kk = 0; kk < NK; kk++)
        #pragma unroll
        for (int c = 0; c < NOUT; c++)
            acc[kk * NOUT + c] = (kk == 0) ? sb[c] : 0.0f;

    for (int k4 = 0; k4 < HID / 4; k4++) {
        float4 hv = hp[k4];
        #pragma unroll
        for (int kk = 0; kk < NK; kk++) {
            const float* w = sW + kk * HID * NOUT + (k4 * 4) * NOUT;
            #pragma unroll
            for (int c = 0; c < NOUT; c++) acc[kk * NOUT + c] += hv.x * w[c];
            #pragma unroll
            for (int c = 0; c < NOUT; c++) acc[kk * NOUT + c] += hv.y * w[NOUT + c];
            #pragma unroll
            for (int c = 0; c < NOUT; c++) acc[kk * NOUT + c] += hv.z * w[2 * NOUT + c];
            #pragma unroll
            for (int c = 0; c < NOUT; c++) acc[kk * NOUT + c] += hv.w * w[3 * NOUT + c];
        }
    }
    float* gs[NK] = {g0 + row * P16, g1 + row * P16, g2 + row * P16, g3 + row * P16};
    #pragma unroll
    for (int kk = 0; kk < NK; kk++) {
        #pragma unroll
        for (int c = 0; c < NOUT; c++) gs[kk][c] = acc[kk * NOUT + c];
        #pragma unroll
        for (int c = NOUT; c < P16; c++) gs[kk][c] = 0.0f;
    }
}

// ---------------- launch ----------------
extern "C" void kernel_launch(void* const* d_in, const int* in_sizes, int n_in,
                              void* d_out, int out_size) {
    const float *x = 0, *pos = 0, *ea = 0, *W1 = 0, *b1 = 0, *W2 = 0, *b2 = 0,
                *W3 = 0, *b3 = 0;
    const int* ei32 = 0;
    for (int i = 0; i < n_in; i++) {
        switch (in_sizes[i]) {
            case 1600000: ei32 = (const int*)d_in[i]; break;
            case  800000: ea  = (const float*)d_in[i]; break;
            case  300000: x   = (const float*)d_in[i]; break;
            case  100000: pos = (const float*)d_in[i]; break;
            case    2048: W1  = (const float*)d_in[i]; break;
            case   16384: W2  = (const float*)d_in[i]; break;
            case    2560: W3  = (const float*)d_in[i]; break;
            case      10: b3  = (const float*)d_in[i]; break;
            case      64:
                if (!b1) b1 = (const float*)d_in[i];
                else     b2 = (const float*)d_in[i];
                break;
            default: break;
        }
    }
    float* out = (float*)d_out;

    Scratch* S;
    cudaGetSymbolAddress((void**)&S, g_s);
    cudaFuncSetAttribute(k_gemm_l2, cudaFuncAttributeMaxDynamicSharedMemorySize,
                         NK * HID * HID * (int)sizeof(float));

    const int BE = (NE + 255) / 256;
    const int BN = (NN + 255) / 256;
    const int BG = (NN + 127) / 128;
    const int BG2 = (NN + 255) / 256;
    const int BW = (NN + 7) / 8;
    const int B8  = (NN + 31) / 32;
    const int B16 = (NN + 15) / 16;

    k_detect<<<1, 1024>>>(ei32);
    k_zero_concat<<<BN, 256>>>(x, pos, S->h0, S->deg, S->cnt);
    k_deg_cnt<<<BE, 256>>>(ei32, ea, S->deg, S->cnt);
    k_scan1<<<NSCANB, 256>>>(S->cnt, S->rowptr, S->bsum);
    k_scan2<<<1, 256>>>(S->bsum);
    k_scan3<<<NSCANB, 256>>>(S->rowptr, S->cursor, S->bsum, S->deg, S->dinv);
    k_fill<<<BE, 256>>>(ei32, ea, S->dinv, S->cursor, S->edg);

    // layer 1 (F=8 -> 64), fp16 output
    k_propW<8><<<B8, 256>>>(S->h0,  nullptr, S->t8a, S->rowptr, S->edg);
    k_propW<8><<<B8, 256>>>(S->t8a, nullptr, S->t8b, S->rowptr, S->edg);
    k_propW<8><<<B8, 256>>>(S->t8b, nullptr, S->t8c, S->rowptr, S->edg);
    k_gemm_l1<<<BG, 128>>>(S->h0, S->t8a, S->t8b, S->t8c, W1, b1, S->h16A);

    // layer 2 hops in fp16 (one 128B line per edge)
    k_prop64h<<<BW, 256>>>(S->h16A, S->h16B, S->rowptr, S->edg);
    k_prop64h<<<BW, 256>>>(S->h16B, S->h16C, S->rowptr, S->edg);
    k_prop64h<<<BW, 256>>>(S->h16C, S->h16D, S->rowptr, S->edg);

    // layer-2 GEMM (fp16 in, fp32 out) then layer-3 transform
    k_gemm_l2<<<BG2, 256, NK * HID * HID * (int)sizeof(float)>>>(
        S->h16A, S->h16B, S->h16C, S->h16D, W2, b2, S->hA);
    k_tx3<<<BG, 128>>>(S->hA, W3, b3, S->g0, S->g1, S->g2, S->g3);

    // layer 3 Horner propagate at width 16 + fused log-softmax
    k_propW<16><<<B16, 256>>>(S->g3,  S->g2, S->p16a, S->rowptr, S->edg);
    k_propW<16><<<B16, 256>>>(S->p16a, S->g1, S->p16b, S->rowptr, S->edg);
    k_prop16_lsm<<<B16, 256>>>(S->p16b, S->g0, out, S->rowptr, S->edg);
}

// round 9
// speedup vs baseline: 1.0834x; 1.0630x over previous
#include <cuda_runtime.h>
#include <cstdint>

#define NN 50000
#define NE 800000
#define FIN 8          // concat(x[6], pos[2])
#define HID 64
#define NOUT 10
#define P16 16         // padded layer-3 feature width
#define NK 4           // K+1 weight slices
#define NSCANB 196     // ceil(NN/256)

typedef unsigned long long ull;

// ---------------- scratch (no allocation allowed) ----------------
struct Scratch {
    alignas(128) float deg[NN];
    alignas(128) float dinv[NN];
    alignas(128) int   cnt[NN];
    alignas(128) int   rowptr[NN + 1];
    alignas(128) int   cursor[NN];
    alignas(128) int   bsum[256];
    alignas(128) int2  edg[NE];           // (src, bitcast(norm))
    alignas(128) float h0 [NN * FIN];
    alignas(128) float t8a[NN * FIN];
    alignas(128) float t8b[NN * FIN];
    alignas(128) float t8c[NN * FIN];
    alignas(128) float hA[NN * HID];
    alignas(128) float hB[NN * HID];
    alignas(128) float hC[NN * HID];
    alignas(128) float hD[NN * HID];
    alignas(128) float g0[NN * P16];
    alignas(128) float g1[NN * P16];
    alignas(128) float g2[NN * P16];
    alignas(128) float g3[NN * P16];
    alignas(128) float p16a[NN * P16];
    alignas(128) float p16b[NN * P16];
};
__device__ Scratch g_s;
__device__ int g_is64;

// ---------------- f32x2 packed helpers ----------------
__device__ __forceinline__ ull dup2(float v) {
    ull r; unsigned int b = __float_as_uint(v);
    asm("mov.b64 %0, {%1, %1};" : "=l"(r) : "r"(b));
    return r;
}
__device__ __forceinline__ void fma2(ull& d, ull a, ull b) {
    asm("fma.rn.f32x2 %0, %1, %2, %0;" : "+l"(d) : "l"(a), "l"(b));
}
__device__ __forceinline__ float2 unpack2(ull v) {
    float2 u;
    asm("mov.b64 {%0, %1}, %2;" : "=f"(u.x), "=f"(u.y) : "l"(v));
    return u;
}

// ---------------- edge_index dtype detection ----------------
__global__ void k_detect(const int* __restrict__ ei32) {
    int t = threadIdx.x;
    const int step = NE / 1024;
    long long idx = 2LL * t * step + 1;
    int nz = (ei32[idx] != 0) ? 1 : 0;
    int any = __syncthreads_or(nz);
    if (t == 0) g_is64 = any ? 0 : 1;
}

__device__ __forceinline__ int load_src(const int* ei32, int e, int is64) {
    int v = is64 ? ei32[2 * e] : ei32[e];
    return min(max(v, 0), NN - 1);
}
__device__ __forceinline__ int load_dst(const int* ei32, int e, int is64) {
    long long base = is64 ? 2LL * ((long long)NE + e) : (long long)NE + e;
    int v = ei32[base];
    return min(max(v, 0), NN - 1);
}

// ---------------- graph preprocessing ----------------
__global__ void k_zero_concat(const float* __restrict__ x, const float* __restrict__ pos,
                              float* __restrict__ h0,
                              float* __restrict__ deg, int* __restrict__ cnt) {
    int i = blockIdx.x * blockDim.x + threadIdx.x;
    if (i >= NN) return;
    deg[i] = 0.0f; cnt[i] = 0;
    float* o = h0 + i * FIN;
    const float* xi = x + i * 6;
    o[0] = xi[0]; o[1] = xi[1]; o[2] = xi[2];
    o[3] = xi[3]; o[4] = xi[4]; o[5] = xi[5];
    o[6] = pos[i * 2 + 0];
    o[7] = pos[i * 2 + 1];
}

__global__ void k_deg_cnt(const int* __restrict__ ei32,
                          const float* __restrict__ ea,
                          float* __restrict__ deg, int* __restrict__ cnt) {
    int e = blockIdx.x * blockDim.x + threadIdx.x;
    if (e >= NE) return;
    int is64 = g_is64;
    int d = load_dst(ei32, e, is64);
    atomicAdd(&deg[d], ea[e]);
    atomicAdd(&cnt[d], 1);
}

__global__ void k_scan1(const int* __restrict__ cnt,
                        int* __restrict__ partial, int* __restrict__ bsum) {
    int i = blockIdx.x * 256 + threadIdx.x;
    int lane = threadIdx.x & 31, wid = threadIdx.x >> 5;
    int v = (i < NN) ? cnt[i] : 0;
    int x = v;
    #pragma unroll
    for (int o = 1; o < 32; o <<= 1) {
        int n = __shfl_up_sync(0xFFFFFFFFu, x, o);
        if (lane >= o) x += n;
    }
    __shared__ int ws[8];
    if (lane == 31) ws[wid] = x;
    __syncthreads();
    if (threadIdx.x < 8) {
        int w = ws[threadIdx.x];
        #pragma unroll
        for (int o = 1; o < 8; o <<= 1) {
            int n = __shfl_up_sync(0xFFu, w, o);
            if ((threadIdx.x & 7) >= o) w += n;
        }
        ws[threadIdx.x] = w;
    }
    __syncthreads();
    int excl = x - v + (wid > 0 ? ws[wid - 1] : 0);
    if (i < NN) partial[i] = excl;
    if (threadIdx.x == 255) bsum[blockIdx.x] = excl + v;
}

__global__ void k_scan2(int* __restrict__ bsum) {
    int t = threadIdx.x;
    int lane = t & 31, wid = t >> 5;
    int v = (t < NSCANB) ? bsum[t] : 0;
    int x = v;
    #pragma unroll
    for (int o = 1; o < 32; o <<= 1) {
        int n = __shfl_up_sync(0xFFFFFFFFu, x, o);
        if (lane >= o) x += n;
    }
    __shared__ int ws[8];
    if (lane == 31) ws[wid] = x;
    __syncthreads();
    if (t < 8) {
        int w = ws[t];
        #pragma unroll
        for (int o = 1; o < 8; o <<= 1) {
            int n = __shfl_up_sync(0xFFu, w, o);
            if ((t & 7) >= o) w += n;
        }
        ws[t] = w;
    }
    __syncthreads();
    int excl = x - v + (wid > 0 ? ws[wid - 1] : 0);
    if (t < NSCANB) bsum[t] = excl;
}

__global__ void k_scan3(int* __restrict__ rowptr, int* __restrict__ cursor,
                        const int* __restrict__ bsum,
                        const float* __restrict__ deg, float* __restrict__ dinv) {
    int i = blockIdx.x * 256 + threadIdx.x;
    if (i >= NN) return;
    int r = rowptr[i] + bsum[blockIdx.x];
    rowptr[i] = r;
    cursor[i] = r;
    float d = deg[i];
    dinv[i] = (d > 0.0f) ? rsqrtf(d) : 0.0f;
    if (i == 0) rowptr[NN] = NE;
}

__global__ void k_fill(const int* __restrict__ ei32,
                       const float* __restrict__ ea,
                       const float* __restrict__ dinv,
                       int* __restrict__ cursor, int2* __restrict__ edg) {
    int e = blockIdx.x * blockDim.x + threadIdx.x;
    if (e >= NE) return;
    int is64 = g_is64;
    int srcv = load_src(ei32, e, is64);
    int dstv = load_dst(ei32, e, is64);
    float nv = dinv[srcv] * ea[e] * dinv[dstv];
    int p = atomicAdd(&cursor[dstv], 1);
    edg[p] = make_int2(srcv, __float_as_int(nv));
}

// ---------------- propagate (CSR gather, pull) ----------------
template<int W>
__global__ void k_propW(const float* __restrict__ h, const float* __restrict__ add,
                        float* __restrict__ o,
                        const int* __restrict__ rowptr, const int2* __restrict__ edg) {
    const int GPW = 32 / W;
    int warp = blockIdx.x * (blockDim.x >> 5) + (threadIdx.x >> 5);
    int lane = threadIdx.x & 31;
    int node = warp * GPW + lane / W;
    int f = lane % W;
    if (node >= NN) return;
    int b = rowptr[node], e = rowptr[node + 1];
    float acc = add ? add[node * W + f] : 0.0f;
    for (int i = b; i < e; i++) {
        int2 ev = edg[i];
        acc += __int_as_float(ev.y) * h[ev.x * W + f];
    }
    o[node * W + f] = acc;
}

// warp per node; lane f covers features {2f, 2f+1} via one LDG.64 + one FFMA2
__global__ void k_prop64(const ull* __restrict__ h, ull* __restrict__ o,
                         const int* __restrict__ rowptr, const int2* __restrict__ edg) {
    int node = blockIdx.x * (blockDim.x >> 5) + (threadIdx.x >> 5);
    int lane = threadIdx.x & 31;
    if (node >= NN) return;
    int b = rowptr[node], e = rowptr[node + 1];
    ull acc = 0;                          // packed {0.f, 0.f}
    #pragma unroll 2
    for (int i = b; i < e; i++) {
        int2 ev = edg[i];                 // broadcast within warp
        ull vd = dup2(__int_as_float(ev.y));
        ull hv = h[ev.x * 32 + lane];     // LDG.64, fully coalesced 256B row
        fma2(acc, hv, vd);
    }
    o[node * 32 + lane] = acc;
}

// final Horner propagate + log_softmax via width-16 shuffle reduction
__global__ void k_prop16_lsm(const float* __restrict__ h, const float* __restrict__ add,
                             float* __restrict__ outp,
                             const int* __restrict__ rowptr, const int2* __restrict__ edg) {
    int warp = blockIdx.x * (blockDim.x >> 5) + (threadIdx.x >> 5);
    int lane = threadIdx.x & 31;
    int node = warp * 2 + (lane >> 4);
    int f = lane & 15;
    if (node >= NN) return;
    int b = rowptr[node], e = rowptr[node + 1];
    float acc = add[node * P16 + f];
    for (int i = b; i < e; i++) {
        int2 ev = edg[i];
        acc += __int_as_float(ev.y) * h[ev.x * P16 + f];
    }
    float mv = (f < NOUT) ? acc : -1e30f;
    #pragma unroll
    for (int o = 8; o >= 1; o >>= 1)
        mv = fmaxf(mv, __shfl_xor_sync(0xFFFFFFFFu, mv, o, 16));
    float ex = (f < NOUT) ? expf(acc - mv) : 0.0f;
    float s = ex;
    #pragma unroll
    for (int o = 8; o >= 1; o >>= 1)
        s += __shfl_xor_sync(0xFFFFFFFFu, s, o, 16);
    float l = mv + logf(s);
    if (f < NOUT) outp[node * NOUT + f] = acc - l;
}

// ---------------- fused layer GEMMs (packed f32x2 FMA) ----------------
__global__ void k_gemm_l1(const float* __restrict__ h0, const float* __restrict__ h1,
                          const float* __restrict__ h2, const float* __restrict__ h3,
                          const float* __restrict__ W, const float* __restrict__ bias,
                          float* __restrict__ outp) {
    __shared__ alignas(16) float sW[NK * FIN * HID];
    __shared__ alignas(16) float sb[HID];
    for (int i = threadIdx.x; i < NK * FIN * HID; i += blockDim.x) sW[i] = W[i];
    if (threadIdx.x < HID) sb[threadIdx.x] = bias[threadIdx.x];
    __syncthreads();

    int row = blockIdx.x * blockDim.x + threadIdx.x;
    if (row >= NN) return;
    const float* hs[NK] = {h0 + row * FIN, h1 + row * FIN, h2 + row * FIN, h3 + row * FIN};

    ull acc2[HID / 2];
    const ull* sb64 = (const ull*)sb;
    #pragma unroll
    for (int c = 0; c < HID / 2; c++) acc2[c] = sb64[c];

    #pragma unroll
    for (int kk = 0; kk < NK; kk++) {
        const float4* hp = (const float4*)hs[kk];
        float4 h04 = hp[0], h14 = hp[1];
        float hv[FIN] = {h04.x, h04.y, h04.z, h04.w, h14.x, h14.y, h14.z, h14.w};
        #pragma unroll
        for (int k = 0; k < FIN; k++) {
            ull hd = dup2(hv[k]);
            const ulonglong2* w2 = (const ulonglong2*)(sW + (kk * FIN + k) * HID);
            #pragma unroll
            for (int c = 0; c < HID / 4; c++) {
                ulonglong2 wp = w2[c];
                fma2(acc2[2 * c], wp.x, hd);
                fma2(acc2[2 * c + 1], wp.y, hd);
            }
        }
    }
    float4* op = (float4*)(outp + row * HID);
    #pragma unroll
    for (int c = 0; c < HID / 4; c++) {
        float2 u0 = unpack2(acc2[2 * c]), u1 = unpack2(acc2[2 * c + 1]);
        op[c] = make_float4(fmaxf(u0.x, 0.f), fmaxf(u0.y, 0.f),
                            fmaxf(u1.x, 0.f), fmaxf(u1.y, 0.f));
    }
}

__global__ void k_gemm_l2(const float* __restrict__ h0, const float* __restrict__ h1,
                          const float* __restrict__ h2, const float* __restrict__ h3,
                          const float* __restrict__ W, const float* __restrict__ bias,
                          float* __restrict__ outp) {
    extern __shared__ float sW[];          // 64KB
    __shared__ alignas(16) float sb[HID];
    for (int i = threadIdx.x; i < NK * HID * HID; i += blockDim.x) sW[i] = W[i];
    if (threadIdx.x < HID) sb[threadIdx.x] = bias[threadIdx.x];
    __syncthreads();

    int row = blockIdx.x * blockDim.x + threadIdx.x;
    if (row >= NN) return;
    const float* hs[NK] = {h0 + row * HID, h1 + row * HID, h2 + row * HID, h3 + row * HID};

    ull acc2[HID / 2];
    const ull* sb64 = (const ull*)sb;
    #pragma unroll
    for (int c = 0; c < HID / 2; c++) acc2[c] = sb64[c];

    for (int kk = 0; kk < NK; kk++) {
        const float4* hp = (const float4*)hs[kk];
        #pragma unroll 4
        for (int k4 = 0; k4 < HID / 4; k4++) {
            float4 hv = hp[k4];
            float hvv[4] = {hv.x, hv.y, hv.z, hv.w};
            #pragma unroll
            for (int j = 0; j < 4; j++) {
                ull hd = dup2(hvv[j]);
                const ulonglong2* w2 =
                    (const ulonglong2*)(sW + (kk * HID + k4 * 4 + j) * HID);
                #pragma unroll
                for (int c = 0; c < HID / 4; c++) {
                    ulonglong2 wp = w2[c];
                    fma2(acc2[2 * c], wp.x, hd);
                    fma2(acc2[2 * c + 1], wp.y, hd);
                }
            }
        }
    }
    float4* op = (float4*)(outp + row * HID);
    #pragma unroll
    for (int c = 0; c < HID / 4; c++) {
        float2 u0 = unpack2(acc2[2 * c]), u1 = unpack2(acc2[2 * c + 1]);
        op[c] = make_float4(fmaxf(u0.x, 0.f), fmaxf(u0.y, 0.f),
                            fmaxf(u1.x, 0.f), fmaxf(u1.y, 0.f));
    }
}

// layer-3 transforms: g_k = h @ W3[k] (bias folded into g0); pad to 16
__global__ void k_tx3(const float* __restrict__ h, const float* __restrict__ W,
                      const float* __restrict__ bias,
                      float* __restrict__ g0, float* __restrict__ g1,
                      float* __restrict__ g2, float* __restrict__ g3) {
    __shared__ float sW[NK * HID * NOUT];
    __shared__ float sb[NOUT];
    for (int i = threadIdx.x; i < NK * HID * NOUT; i += blockDim.x) sW[i] = W[i];
    if (threadIdx.x < NOUT) sb[threadIdx.x] = bias[threadIdx.x];
    __syncthreads();

    int row = blockIdx.x * blockDim.x + threadIdx.x;
    if (row >= NN) return;
    const float4* hp = (const float4*)(h + row * HID);

    float acc[NK * NOUT];
    #pragma unroll
    for (int kk = 0; kk < NK; kk++)
        #pragma unroll
        for (int c = 0; c < NOUT; c++)
            acc[kk * NOUT + c] = (kk == 0) ? sb[c] : 0.0f;

    for (int k4 = 0; k4 < HID / 4; k4++) {
        float4 hv = hp[k4];
        #pragma unroll
        for (int kk = 0; kk < NK; kk++) {
            const float* w = sW + kk * HID * NOUT + (k4 * 4) * NOUT;
            #pragma unroll
            for (int c = 0; c < NOUT; c++) acc[kk * NOUT + c] += hv.x * w[c];
            #pragma unroll
            for (int c = 0; c < NOUT; c++) acc[kk * NOUT + c] += hv.y * w[NOUT + c];
            #pragma unroll
            for (int c = 0; c < NOUT; c++) acc[kk * NOUT + c] += hv.z * w[2 * NOUT + c];
            #pragma unroll
            for (int c = 0; c < NOUT; c++) acc[kk * NOUT + c] += hv.w * w[3 * NOUT + c];
        }
    }
    float* gs[NK] = {g0 + row * P16, g1 + row * P16, g2 + row * P16, g3 + row * P16};
    #pragma unroll
    for (int kk = 0; kk < NK; kk++) {
        #pragma unroll
        for (int c = 0; c < NOUT; c++) gs[kk][c] = acc[kk * NOUT + c];
        #pragma unroll
        for (int c = NOUT; c < P16; c++) gs[kk][c] = 0.0f;
    }
}

// ---------------- launch ----------------
extern "C" void kernel_launch(void* const* d_in, const int* in_sizes, int n_in,
                              void* d_out, int out_size) {
    const float *x = 0, *pos = 0, *ea = 0, *W1 = 0, *b1 = 0, *W2 = 0, *b2 = 0,
                *W3 = 0, *b3 = 0;
    const int* ei32 = 0;
    for (int i = 0; i < n_in; i++) {
        switch (in_sizes[i]) {
            case 1600000: ei32 = (const int*)d_in[i]; break;
            case  800000: ea  = (const float*)d_in[i]; break;
            case  300000: x   = (const float*)d_in[i]; break;
            case  100000: pos = (const float*)d_in[i]; break;
            case    2048: W1  = (const float*)d_in[i]; break;
            case   16384: W2  = (const float*)d_in[i]; break;
            case    2560: W3  = (const float*)d_in[i]; break;
            case      10: b3  = (const float*)d_in[i]; break;
            case      64:
                if (!b1) b1 = (const float*)d_in[i];
                else     b2 = (const float*)d_in[i];
                break;
            default: break;
        }
    }
    float* out = (float*)d_out;

    Scratch* S;
    cudaGetSymbolAddress((void**)&S, g_s);
    cudaFuncSetAttribute(k_gemm_l2, cudaFuncAttributeMaxDynamicSharedMemorySize,
                         NK * HID * HID * (int)sizeof(float));

    const int BE = (NE + 255) / 256;
    const int BN = (NN + 255) / 256;
    const int BG = (NN + 127) / 128;
    const int BG2 = (NN + 255) / 256;
    const int BW = (NN + 7) / 8;
    const int B8  = (NN + 31) / 32;
    const int B16 = (NN + 15) / 16;

    k_detect<<<1, 1024>>>(ei32);
    k_zero_concat<<<BN, 256>>>(x, pos, S->h0, S->deg, S->cnt);
    k_deg_cnt<<<BE, 256>>>(ei32, ea, S->deg, S->cnt);
    k_scan1<<<NSCANB, 256>>>(S->cnt, S->rowptr, S->bsum);
    k_scan2<<<1, 256>>>(S->bsum);
    k_scan3<<<NSCANB, 256>>>(S->rowptr, S->cursor, S->bsum, S->deg, S->dinv);
    k_fill<<<BE, 256>>>(ei32, ea, S->dinv, S->cursor, S->edg);

    // layer 1 (F=8 -> 64)
    k_propW<8><<<B8, 256>>>(S->h0,  nullptr, S->t8a, S->rowptr, S->edg);
    k_propW<8><<<B8, 256>>>(S->t8a, nullptr, S->t8b, S->rowptr, S->edg);
    k_propW<8><<<B8, 256>>>(S->t8b, nullptr, S->t8c, S->rowptr, S->edg);
    k_gemm_l1<<<BG, 128>>>(S->h0, S->t8a, S->t8b, S->t8c, W1, b1, S->hA);

    // layer 2 hops (fp32, LDG.64 + FFMA2 inner loop)
    k_prop64<<<BW, 256>>>((const ull*)S->hA, (ull*)S->hB, S->rowptr, S->edg);
    k_prop64<<<BW, 256>>>((const ull*)S->hB, (ull*)S->hC, S->rowptr, S->edg);
    k_prop64<<<BW, 256>>>((const ull*)S->hC, (ull*)S->hD, S->rowptr, S->edg);
    k_gemm_l2<<<BG2, 256, NK * HID * HID * (int)sizeof(float)>>>(
        S->hA, S->hB, S->hC, S->hD, W2, b2, S->hA);

    // layer 3 (64 -> 10): transform first, then Horner propagate at width 16
    k_tx3<<<BG, 128>>>(S->hA, W3, b3, S->g0, S->g1, S->g2, S->g3);
    k_propW<16><<<B16, 256>>>(S->g3,  S->g2, S->p16a, S->rowptr, S->edg);
    k_propW<16><<<B16, 256>>>(S->p16a, S->g1, S->p16b, S->rowptr, S->edg);
    k_prop16_lsm<<<B16, 256>>>(S->p16b, S->g0, out, S->rowptr, S->edg);
}